// round 5
// baseline (speedup 1.0000x reference)
#include <cuda_runtime.h>
#include <cuda_bf16.h>
#include <math.h>
#include <stdint.h>

// ---------------- problem constants ----------------
#define NTOK 4096          // B*L
#define DDIM 768           // D
#define NEXP 8             // E
#define HDIM 2048          // H
#define CAP  614           // int(1.2*4096/8)
#define MAXROWS (2*CAP)    // 1228 rows per expert max (k=0 and k=1 slots)

#define NX  (NTOK*DDIM)            // 3,145,728
#define NW1 (NEXP*DDIM*2*HDIM)     // 25,165,824
#define NW2 (NEXP*HDIM*DDIM)       // 12,582,912

// ---------------- device scratch (static, no allocs) ----------------
__device__ int   g_ridx[NTOK][2];
__device__ float g_rw[NTOK][2];
__device__ int   g_rowtok[NEXP][MAXROWS];
__device__ float g_roww[NEXP][MAXROWS];
__device__ int   g_rowcnt[NEXP];
__device__ float g_act[NEXP][MAXROWS][HDIM];   // ~80 MB (tf32-rounded)
__device__ float g_xr[NX];                     // tf32-rounded x   (~12.6 MB)
__device__ float g_w1r[NW1];                   // tf32-rounded W1  (~100 MB)
__device__ float g_w2r[NW2];                   // tf32-rounded W2  (~50 MB)

// ---------------- helpers ----------------
__device__ __forceinline__ float tf32r(float x) {
    unsigned r;
    asm("cvt.rna.tf32.f32 %0, %1;" : "=r"(r) : "f"(x));
    return __uint_as_float(r);
}
__device__ __forceinline__ unsigned fau(float x) { return __float_as_uint(x); }

__device__ __forceinline__ void mma_tf32(float c[4], const unsigned a[4], const unsigned b[2]) {
    asm volatile(
        "mma.sync.aligned.m16n8k8.row.col.f32.tf32.tf32.f32 "
        "{%0,%1,%2,%3}, {%4,%5,%6,%7}, {%8,%9}, {%0,%1,%2,%3};"
        : "+f"(c[0]), "+f"(c[1]), "+f"(c[2]), "+f"(c[3])
        : "r"(a[0]), "r"(a[1]), "r"(a[2]), "r"(a[3]), "r"(b[0]), "r"(b[1]));
}

__device__ __forceinline__ uint32_t sptr(const void* p) {
    return (uint32_t)__cvta_generic_to_shared(p);
}
// 16-byte async copy; sz=0 -> zero-fill destination
__device__ __forceinline__ void cp_async16(uint32_t dst, const void* src, int sz) {
    asm volatile("cp.async.cg.shared.global [%0], [%1], 16, %2;"
                 :: "r"(dst), "l"(src), "r"(sz));
}
__device__ __forceinline__ void cp_commit() { asm volatile("cp.async.commit_group;"); }
__device__ __forceinline__ void cp_wait1()  { asm volatile("cp.async.wait_group 1;"); }
__device__ __forceinline__ void cp_wait0()  { asm volatile("cp.async.wait_group 0;"); }

// ---------------- kernel 0a: pre-round x, W1, W2 to tf32 (RNA) ----------------
__global__ void preround_kernel(const float* __restrict__ x,
                                const float* __restrict__ W1,
                                const float* __restrict__ W2) {
    const int n4x = NX / 4, n4w1 = NW1 / 4, n4w2 = NW2 / 4;
    const int total = n4x + n4w1 + n4w2;
    for (int i = blockIdx.x * blockDim.x + threadIdx.x; i < total; i += gridDim.x * blockDim.x) {
        const float4* src; float4* dst; int j;
        if (i < n4x)              { src = (const float4*)x;  dst = (float4*)g_xr;  j = i; }
        else if (i < n4x + n4w1)  { src = (const float4*)W1; dst = (float4*)g_w1r; j = i - n4x; }
        else                      { src = (const float4*)W2; dst = (float4*)g_w2r; j = i - n4x - n4w1; }
        float4 v = src[j];
        dst[j] = make_float4(tf32r(v.x), tf32r(v.y), tf32r(v.z), tf32r(v.w));
    }
}

// ---------------- kernel 0b: zero the output (scatter target) ----------------
__global__ void zero_out_kernel(float* __restrict__ out) {
    float4* p = reinterpret_cast<float4*>(out);
    const int n = NTOK * DDIM / 4;
    for (int i = blockIdx.x * blockDim.x + threadIdx.x; i < n; i += gridDim.x * blockDim.x) {
        p[i] = make_float4(0.f, 0.f, 0.f, 0.f);
    }
}

// ---------------- kernel 1: router (one warp per token) ----------------
__global__ __launch_bounds__(256) void router_kernel(const float* __restrict__ x,
                                                     const float* __restrict__ Wg) {
    int warp = (blockIdx.x * blockDim.x + threadIdx.x) >> 5;
    int lane = threadIdx.x & 31;
    if (warp >= NTOK) return;
    const float* xr = x + (size_t)warp * DDIM;
    float acc[NEXP];
#pragma unroll
    for (int e = 0; e < NEXP; e++) acc[e] = 0.f;
    for (int d = lane; d < DDIM; d += 32) {
        float xv = xr[d];
        const float* wr = Wg + d * NEXP;
#pragma unroll
        for (int e = 0; e < NEXP; e++) acc[e] += xv * wr[e];
    }
#pragma unroll
    for (int off = 16; off; off >>= 1) {
#pragma unroll
        for (int e = 0; e < NEXP; e++)
            acc[e] += __shfl_xor_sync(0xffffffffu, acc[e], off);
    }
    if (lane == 0) {
        int e0 = 0; float s0 = acc[0];
#pragma unroll
        for (int e = 1; e < NEXP; e++) if (acc[e] > s0) { s0 = acc[e]; e0 = e; }
        int e1 = -1; float s1 = -INFINITY;
#pragma unroll
        for (int e = 0; e < NEXP; e++) {
            if (e == e0) continue;
            if (acc[e] > s1) { s1 = acc[e]; e1 = e; }
        }
        float x1 = expf(s1 - s0);
        float inv = 1.f / (1.f + x1);
        g_ridx[warp][0] = e0; g_ridx[warp][1] = e1;
        g_rw[warp][0] = inv;  g_rw[warp][1] = x1 * inv;
    }
}

// ---------------- kernel 2: dispatch (stable ordered positions, 1 block) ----------------
__global__ __launch_bounds__(256) void schedule_kernel() {
    __shared__ int scnt[256][16];
    const int t = threadIdx.x;
    int cnt[16];
#pragma unroll
    for (int c = 0; c < 16; c++) cnt[c] = 0;
    const int tok0 = t * 16;
    for (int i = 0; i < 16; i++) {
        int tok = tok0 + i;
        cnt[g_ridx[tok][0]]++;
        cnt[8 + g_ridx[tok][1]]++;
    }
#pragma unroll
    for (int c = 0; c < 16; c++) scnt[t][c] = cnt[c];
    __syncthreads();
    for (int off = 1; off < 256; off <<= 1) {
        int v[16];
        if (t >= off) {
#pragma unroll
            for (int c = 0; c < 16; c++) v[c] = scnt[t - off][c];
        }
        __syncthreads();
        if (t >= off) {
#pragma unroll
            for (int c = 0; c < 16; c++) scnt[t][c] += v[c];
        }
        __syncthreads();
    }
    int base[16];
#pragma unroll
    for (int c = 0; c < 16; c++) base[c] = (t > 0) ? scnt[t - 1][c] : 0;
    int c0cl[8];
#pragma unroll
    for (int e = 0; e < 8; e++) c0cl[e] = min(scnt[255][e], CAP);

    for (int i = 0; i < 16; i++) {
        int tok = tok0 + i;
#pragma unroll
        for (int k = 0; k < 2; k++) {
            int ex = g_ridx[tok][k];
            int c = k * 8 + ex;
            int pos = base[c]++;
            if (pos < CAP) {
                int r = (k == 0) ? pos : (c0cl[ex] + pos);
                g_rowtok[ex][r] = tok;
                g_roww[ex][r] = g_rw[tok][k];
            }
        }
    }
    if (t < 8) g_rowcnt[t] = min(scnt[255][t], CAP) + min(scnt[255][8 + t], CAP);
}

// ---------------- GEMM tile config ----------------
#define BM 128
#define BN 64
#define BK 32
#define AS_STR (BK + 4)   // 36 floats, 144B (16B multiple)
#define BS_STR (BN + 8)   // 72 floats, 288B (16B multiple)
// 256 threads = 8 warps in 4(m) x 2(n); warp tile 32x32

// ---------------- kernel 3: fused GEMM1 + SiLU, cp.async double-buffered ----------------
// dyn smem layout: As[2][BM][36] | Bs1[2][BK][72] | Bs2[2][BK][72]
#define G1_SMEM ((2*BM*AS_STR + 4*BK*BS_STR) * 4)
__global__ __launch_bounds__(256, 2) void gemm_h_fused_kernel() {
    const int e  = blockIdx.z;
    const int M  = g_rowcnt[e];
    const int m0 = blockIdx.y * BM;
    if (m0 >= M) return;
    const int n0 = blockIdx.x * BN;

    extern __shared__ float sm[];
    float* Asm = sm;                              // 2*BM*AS_STR
    float* Bs1 = sm + 2 * BM * AS_STR;            // 2*BK*BS_STR
    float* Bs2 = Bs1 + 2 * BK * BS_STR;           // 2*BK*BS_STR
    __shared__ int stok[BM];

    const int t = threadIdx.x;
    if (t < BM) {
        int r = m0 + t;
        stok[t] = (r < M) ? g_rowtok[e][r] : -1;
    }
    __syncthreads();

    const float* Bg = g_w1r + (size_t)e * DDIM * (2 * HDIM);

    const int la_row = t >> 3;          // 0..31
    const int la_k   = (t & 7) << 2;    // 0,4,...,28
    const int lb_k   = t >> 3;          // 0..31
    const int lb_n   = (t & 7) << 3;    // 0,8,...,56

    int tokp[4];
#pragma unroll
    for (int p = 0; p < 4; p++) tokp[p] = stok[p * 32 + la_row];

    auto load_tile = [&](int s, int k0) {
#pragma unroll
        for (int p = 0; p < 4; p++) {
            int row = p * 32 + la_row;
            int tok = tokp[p];
            uint32_t dst = sptr(&Asm[s * BM * AS_STR + row * AS_STR + la_k]);
            const float* src = (tok >= 0) ? (g_xr + (size_t)tok * DDIM + k0 + la_k) : g_xr;
            cp_async16(dst, src, tok >= 0 ? 16 : 0);
        }
        const float* brow = Bg + (size_t)(k0 + lb_k) * (2 * HDIM) + n0 + lb_n;
        uint32_t d1 = sptr(&Bs1[s * BK * BS_STR + lb_k * BS_STR + lb_n]);
        uint32_t d2 = sptr(&Bs2[s * BK * BS_STR + lb_k * BS_STR + lb_n]);
        cp_async16(d1,      brow,            16);
        cp_async16(d1 + 16, brow + 4,        16);
        cp_async16(d2,      brow + HDIM,     16);
        cp_async16(d2 + 16, brow + HDIM + 4, 16);
    };

    float accU[8][4], accG[8][4];
#pragma unroll
    for (int i = 0; i < 8; i++)
#pragma unroll
        for (int j = 0; j < 4; j++) { accU[i][j] = 0.f; accG[i][j] = 0.f; }

    const int warp = t >> 5, lane = t & 31;
    const int wm = warp & 3, wn = warp >> 2;
    const int gid = lane >> 2, tg = lane & 3;

    const int NT = DDIM / BK;   // 24
    load_tile(0, 0);
    cp_commit();

    for (int kt = 0; kt < NT; kt++) {
        const int cur = kt & 1;
        if (kt + 1 < NT) { load_tile((kt + 1) & 1, (kt + 1) * BK); cp_commit(); cp_wait1(); }
        else             { cp_wait0(); }
        __syncthreads();

        const float* A  = &Asm[cur * BM * AS_STR];
        const float* B1 = &Bs1[cur * BK * BS_STR];
        const float* B2 = &Bs2[cur * BK * BS_STR];
#pragma unroll
        for (int ks = 0; ks < 4; ks++) {
            const int kk = ks * 8;
            unsigned a[2][4], b1[4][2], b2[4][2];
#pragma unroll
            for (int mt = 0; mt < 2; mt++) {
                int rm = wm * 32 + mt * 16;
                a[mt][0] = fau(A[(rm + gid) * AS_STR + kk + tg]);
                a[mt][1] = fau(A[(rm + 8 + gid) * AS_STR + kk + tg]);
                a[mt][2] = fau(A[(rm + gid) * AS_STR + kk + tg + 4]);
                a[mt][3] = fau(A[(rm + 8 + gid) * AS_STR + kk + tg + 4]);
            }
#pragma unroll
            for (int nt = 0; nt < 4; nt++) {
                int nn = wn * 32 + nt * 8;
                b1[nt][0] = fau(B1[(kk + tg) * BS_STR + nn + gid]);
                b1[nt][1] = fau(B1[(kk + tg + 4) * BS_STR + nn + gid]);
                b2[nt][0] = fau(B2[(kk + tg) * BS_STR + nn + gid]);
                b2[nt][1] = fau(B2[(kk + tg + 4) * BS_STR + nn + gid]);
            }
#pragma unroll
            for (int mt = 0; mt < 2; mt++)
#pragma unroll
                for (int nt = 0; nt < 4; nt++) {
                    mma_tf32(accU[mt * 4 + nt], a[mt], b1[nt]);
                    mma_tf32(accG[mt * 4 + nt], a[mt], b2[nt]);
                }
        }
        __syncthreads();
    }

    // epilogue: act = U * silu(G), tf32-rounded -> g_act
#pragma unroll
    for (int mt = 0; mt < 2; mt++) {
        int r0 = m0 + wm * 32 + mt * 16 + gid;
#pragma unroll
        for (int nt = 0; nt < 4; nt++) {
            int col = n0 + wn * 32 + nt * 8 + 2 * tg;
            float* u = accU[mt * 4 + nt];
            float* g = accG[mt * 4 + nt];
            if (r0 < M) {
                float2 v;
                v.x = tf32r(u[0] * (g[0] / (1.f + expf(-g[0]))));
                v.y = tf32r(u[1] * (g[1] / (1.f + expf(-g[1]))));
                *(float2*)&g_act[e][r0][col] = v;
            }
            if (r0 + 8 < M) {
                float2 v;
                v.x = tf32r(u[2] * (g[2] / (1.f + expf(-g[2]))));
                v.y = tf32r(u[3] * (g[3] / (1.f + expf(-g[3]))));
                *(float2*)&g_act[e][r0 + 8][col] = v;
            }
        }
    }
}

// ---------------- kernel 4: y = act @ W2[e], weighted atomic scatter to out ----------------
// dyn smem layout: As[2][BM][36] | Bs[2][BK][72]
#define G2_SMEM ((2*BM*AS_STR + 2*BK*BS_STR) * 4)
__global__ __launch_bounds__(256, 2) void gemm_o_kernel(float* __restrict__ out) {
    const int e  = blockIdx.z;
    const int M  = g_rowcnt[e];
    const int m0 = blockIdx.y * BM;
    if (m0 >= M) return;
    const int n0 = blockIdx.x * BN;

    extern __shared__ float sm[];
    float* Asm = sm;
    float* Bs  = sm + 2 * BM * AS_STR;

    const int t = threadIdx.x;
    const float* Bg = g_w2r + (size_t)e * HDIM * DDIM;

    const int la_row = t >> 3;
    const int la_k   = (t & 7) << 2;
    const int lb_k   = t >> 3;
    const int lb_n   = (t & 7) << 3;

    auto load_tile = [&](int s, int k0) {
#pragma unroll
        for (int p = 0; p < 4; p++) {
            int row = p * 32 + la_row;
            bool ok = (m0 + row) < M;
            uint32_t dst = sptr(&Asm[s * BM * AS_STR + row * AS_STR + la_k]);
            const float* src = ok ? &g_act[e][m0 + row][k0 + la_k] : &g_act[0][0][0];
            cp_async16(dst, src, ok ? 16 : 0);
        }
        const float* brow = Bg + (size_t)(k0 + lb_k) * DDIM + n0 + lb_n;
        uint32_t d1 = sptr(&Bs[s * BK * BS_STR + lb_k * BS_STR + lb_n]);
        cp_async16(d1,      brow,     16);
        cp_async16(d1 + 16, brow + 4, 16);
    };

    float acc[8][4];
#pragma unroll
    for (int i = 0; i < 8; i++)
#pragma unroll
        for (int j = 0; j < 4; j++) acc[i][j] = 0.f;

    const int warp = t >> 5, lane = t & 31;
    const int wm = warp & 3, wn = warp >> 2;
    const int gid = lane >> 2, tg = lane & 3;

    const int NT = HDIM / BK;   // 64
    load_tile(0, 0);
    cp_commit();

    for (int kt = 0; kt < NT; kt++) {
        const int cur = kt & 1;
        if (kt + 1 < NT) { load_tile((kt + 1) & 1, (kt + 1) * BK); cp_commit(); cp_wait1(); }
        else             { cp_wait0(); }
        __syncthreads();

        const float* A = &Asm[cur * BM * AS_STR];
        const float* B = &Bs[cur * BK * BS_STR];
#pragma unroll
        for (int ks = 0; ks < 4; ks++) {
            const int kk = ks * 8;
            unsigned a[2][4], b[4][2];
#pragma unroll
            for (int mt = 0; mt < 2; mt++) {
                int rm = wm * 32 + mt * 16;
                a[mt][0] = fau(A[(rm + gid) * AS_STR + kk + tg]);
                a[mt][1] = fau(A[(rm + 8 + gid) * AS_STR + kk + tg]);
                a[mt][2] = fau(A[(rm + gid) * AS_STR + kk + tg + 4]);
                a[mt][3] = fau(A[(rm + 8 + gid) * AS_STR + kk + tg + 4]);
            }
#pragma unroll
            for (int nt = 0; nt < 4; nt++) {
                int nn = wn * 32 + nt * 8;
                b[nt][0] = fau(B[(kk + tg) * BS_STR + nn + gid]);
                b[nt][1] = fau(B[(kk + tg + 4) * BS_STR + nn + gid]);
            }
#pragma unroll
            for (int mt = 0; mt < 2; mt++)
#pragma unroll
                for (int nt = 0; nt < 4; nt++)
                    mma_tf32(acc[mt * 4 + nt], a[mt], b[nt]);
        }
        __syncthreads();
    }

    // epilogue: weighted atomic scatter into out.
    // Each (token, col) receives at most 2 contributions (k=0, k=1); fp add is
    // commutative, so the result is bitwise deterministic regardless of order.
#pragma unroll
    for (int mt = 0; mt < 2; mt++) {
        int rA = m0 + wm * 32 + mt * 16 + gid;
        int rB = rA + 8;
        float wA = 0.f, wB = 0.f;
        int tokA = 0, tokB = 0;
        if (rA < M) { wA = g_roww[e][rA]; tokA = g_rowtok[e][rA]; }
        if (rB < M) { wB = g_roww[e][rB]; tokB = g_rowtok[e][rB]; }
#pragma unroll
        for (int nt = 0; nt < 4; nt++) {
            int col = n0 + wn * 32 + nt * 8 + 2 * tg;
            float* c = acc[mt * 4 + nt];
            if (rA < M) {
                atomicAdd(&out[(size_t)tokA * DDIM + col],     wA * c[0]);
                atomicAdd(&out[(size_t)tokA * DDIM + col + 1], wA * c[1]);
            }
            if (rB < M) {
                atomicAdd(&out[(size_t)tokB * DDIM + col],     wB * c[2]);
                atomicAdd(&out[(size_t)tokB * DDIM + col + 1], wB * c[3]);
            }
        }
    }
}

// ---------------- launch ----------------
extern "C" void kernel_launch(void* const* d_in, const int* in_sizes, int n_in,
                              void* d_out, int out_size) {
    const float* x  = (const float*)d_in[0];   // (2,2048,768) f32
    const float* Wg = (const float*)d_in[1];   // (768,8)      f32
    const float* W1 = (const float*)d_in[2];   // (8,768,4096) f32
    const float* W2 = (const float*)d_in[3];   // (8,2048,768) f32
    float* out = (float*)d_out;                // (2,2048,768) f32

    cudaFuncSetAttribute(gemm_h_fused_kernel,
                         cudaFuncAttributeMaxDynamicSharedMemorySize, G1_SMEM);
    cudaFuncSetAttribute(gemm_o_kernel,
                         cudaFuncAttributeMaxDynamicSharedMemorySize, G2_SMEM);

    preround_kernel<<<4096, 256>>>(x, W1, W2);
    zero_out_kernel<<<1024, 256>>>(out);
    router_kernel<<<(NTOK * 32) / 256, 256>>>(x, Wg);
    schedule_kernel<<<1, 256>>>();
    gemm_h_fused_kernel<<<dim3(HDIM / BN, (MAXROWS + BM - 1) / BM, NEXP), 256, G1_SMEM>>>();
    gemm_o_kernel<<<dim3(DDIM / BN, (MAXROWS + BM - 1) / BM, NEXP), 256, G2_SMEM>>>(out);
}

// round 6
// speedup vs baseline: 1.0652x; 1.0652x over previous
#include <cuda_runtime.h>
#include <cuda_bf16.h>
#include <math.h>
#include <stdint.h>

// ---------------- problem constants ----------------
#define NTOK 4096          // B*L
#define DDIM 768           // D
#define NEXP 8             // E
#define HDIM 2048          // H
#define CAP  614           // int(1.2*4096/8)
#define MAXROWS (2*CAP)    // 1228 rows per expert max (k=0 and k=1 slots)

#define NX  (NTOK*DDIM)            // 3,145,728
#define NW1 (NEXP*DDIM*2*HDIM)     // 25,165,824
#define NW2 (NEXP*HDIM*DDIM)       // 12,582,912

// ---------------- device scratch (static, no allocs) ----------------
__device__ int   g_ridx[NTOK][2];
__device__ float g_rw[NTOK][2];
__device__ int   g_rowtok[NEXP][MAXROWS];
__device__ float g_roww[NEXP][MAXROWS];
__device__ int   g_rowcnt[NEXP];
__device__ int   g_chcnt[16];                  // per-(k,e) channel totals
__device__ float g_act[NEXP][MAXROWS][HDIM];   // ~80 MB (tf32-rounded)
__device__ float g_xr[NX];                     // tf32-rounded x   (~12.6 MB)
__device__ float g_w1r[NW1];                   // tf32-rounded W1  (~100 MB)
__device__ float g_w2r[NW2];                   // tf32-rounded W2  (~50 MB)

// ---------------- helpers ----------------
__device__ __forceinline__ float tf32r(float x) {
    unsigned r;
    asm("cvt.rna.tf32.f32 %0, %1;" : "=r"(r) : "f"(x));
    return __uint_as_float(r);
}
__device__ __forceinline__ unsigned fau(float x) { return __float_as_uint(x); }

__device__ __forceinline__ void mma_tf32(float c[4], const unsigned a[4], const unsigned b[2]) {
    asm volatile(
        "mma.sync.aligned.m16n8k8.row.col.f32.tf32.tf32.f32 "
        "{%0,%1,%2,%3}, {%4,%5,%6,%7}, {%8,%9}, {%0,%1,%2,%3};"
        : "+f"(c[0]), "+f"(c[1]), "+f"(c[2]), "+f"(c[3])
        : "r"(a[0]), "r"(a[1]), "r"(a[2]), "r"(a[3]), "r"(b[0]), "r"(b[1]));
}

__device__ __forceinline__ uint32_t sptr(const void* p) {
    return (uint32_t)__cvta_generic_to_shared(p);
}
// 16-byte async copy; sz=0 -> zero-fill destination
__device__ __forceinline__ void cp_async16(uint32_t dst, const void* src, int sz) {
    asm volatile("cp.async.cg.shared.global [%0], [%1], 16, %2;"
                 :: "r"(dst), "l"(src), "r"(sz));
}
__device__ __forceinline__ void cp_commit() { asm volatile("cp.async.commit_group;"); }
__device__ __forceinline__ void cp_wait1()  { asm volatile("cp.async.wait_group 1;"); }
__device__ __forceinline__ void cp_wait0()  { asm volatile("cp.async.wait_group 0;"); }

// ---------------- kernel 0: pre-round x/W1/W2 to tf32, zero out + chcnt ----------------
__global__ void preround_kernel(const float* __restrict__ x,
                                const float* __restrict__ W1,
                                const float* __restrict__ W2,
                                float* __restrict__ out) {
    const int gtid = blockIdx.x * blockDim.x + threadIdx.x;
    if (gtid < 16) g_chcnt[gtid] = 0;
    const int n4x = NX / 4, n4w1 = NW1 / 4, n4w2 = NW2 / 4, n4o = NTOK * DDIM / 4;
    const int total = n4x + n4w1 + n4w2 + n4o;
    for (int i = gtid; i < total; i += gridDim.x * blockDim.x) {
        if (i < n4x + n4w1 + n4w2) {
            const float4* src; float4* dst; int j;
            if (i < n4x)              { src = (const float4*)x;  dst = (float4*)g_xr;  j = i; }
            else if (i < n4x + n4w1)  { src = (const float4*)W1; dst = (float4*)g_w1r; j = i - n4x; }
            else                      { src = (const float4*)W2; dst = (float4*)g_w2r; j = i - n4x - n4w1; }
            float4 v = src[j];
            dst[j] = make_float4(tf32r(v.x), tf32r(v.y), tf32r(v.z), tf32r(v.w));
        } else {
            ((float4*)out)[i - (n4x + n4w1 + n4w2)] = make_float4(0.f, 0.f, 0.f, 0.f);
        }
    }
}

// ---------------- kernel 1: router (one warp per token) ----------------
__global__ __launch_bounds__(256) void router_kernel(const float* __restrict__ x,
                                                     const float* __restrict__ Wg) {
    int warp = (blockIdx.x * blockDim.x + threadIdx.x) >> 5;
    int lane = threadIdx.x & 31;
    if (warp >= NTOK) return;
    const float* xr = x + (size_t)warp * DDIM;
    float acc[NEXP];
#pragma unroll
    for (int e = 0; e < NEXP; e++) acc[e] = 0.f;
    for (int d = lane; d < DDIM; d += 32) {
        float xv = xr[d];
        const float* wr = Wg + d * NEXP;
#pragma unroll
        for (int e = 0; e < NEXP; e++) acc[e] += xv * wr[e];
    }
#pragma unroll
    for (int off = 16; off; off >>= 1) {
#pragma unroll
        for (int e = 0; e < NEXP; e++)
            acc[e] += __shfl_xor_sync(0xffffffffu, acc[e], off);
    }
    if (lane == 0) {
        int e0 = 0; float s0 = acc[0];
#pragma unroll
        for (int e = 1; e < NEXP; e++) if (acc[e] > s0) { s0 = acc[e]; e0 = e; }
        int e1 = -1; float s1 = -INFINITY;
#pragma unroll
        for (int e = 0; e < NEXP; e++) {
            if (e == e0) continue;
            if (acc[e] > s1) { s1 = acc[e]; e1 = e; }
        }
        float x1 = expf(s1 - s0);
        float inv = 1.f / (1.f + x1);
        g_ridx[warp][0] = e0; g_ridx[warp][1] = e1;
        g_rw[warp][0] = inv;  g_rw[warp][1] = x1 * inv;
    }
}

// ---------------- kernel 2a: per-channel totals (integer atomics, deterministic) ----------------
__global__ __launch_bounds__(256) void count_kernel() {
    __shared__ int sc[16];
    const int t = threadIdx.x;
    if (t < 16) sc[t] = 0;
    __syncthreads();
    for (int tok = blockIdx.x * blockDim.x + t; tok < NTOK; tok += gridDim.x * blockDim.x) {
        atomicAdd(&sc[g_ridx[tok][0]], 1);
        atomicAdd(&sc[8 + g_ridx[tok][1]], 1);
    }
    __syncthreads();
    if (t < 16 && sc[t]) atomicAdd(&g_chcnt[t], sc[t]);
}

// ---------------- kernel 2b: fill rows (one block per (k,e) channel) ----------------
// Position of token t in channel c = #{t' < t : channel(t')==c}  (token-order stable,
// identical to the reference cumsum). Rows for a channel are contiguous -> coalesced.
__global__ __launch_bounds__(256) void fill_kernel() {
    const int c = blockIdx.x;          // 0..15
    const int k = c >> 3, e = c & 7;
    const int t = threadIdx.x;
    const int lane = t & 31, wid = t >> 5;

    // per-thread membership over its 16 consecutive tokens
    const int tok0 = t * 16;
    int flags = 0, cnt = 0;
#pragma unroll
    for (int i = 0; i < 16; i++) {
        int m = (g_ridx[tok0 + i][k] == e);
        flags |= m << i;
        cnt += m;
    }
    // block exclusive scan of cnt
    int v = cnt;
#pragma unroll
    for (int off = 1; off < 32; off <<= 1) {
        int n = __shfl_up_sync(0xffffffffu, v, off);
        if (lane >= off) v += n;
    }
    __shared__ int wsum[8];
    if (lane == 31) wsum[wid] = v;
    __syncthreads();
    if (t == 0) {
        int s = 0;
#pragma unroll
        for (int i = 0; i < 8; i++) { int x = wsum[i]; wsum[i] = s; s += x; }
    }
    __syncthreads();
    int pos = wsum[wid] + v - cnt;     // channel-relative exclusive prefix

    const int base = (k == 1) ? min(g_chcnt[e], CAP) : 0;
#pragma unroll
    for (int i = 0; i < 16; i++) {
        if ((flags >> i) & 1) {
            if (pos < CAP) {
                int r = base + pos;
                g_rowtok[e][r] = tok0 + i;
                g_roww[e][r] = g_rw[tok0 + i][k];
            }
            pos++;
        }
    }
    if (t == 0 && k == 0)
        g_rowcnt[e] = min(g_chcnt[e], CAP) + min(g_chcnt[8 + e], CAP);
}

// ---------------- GEMM tile config ----------------
#define BM 128
#define BN 64
#define BK 32
#define AS_STR (BK + 4)   // 36 floats, 144B (16B multiple)
#define BS_STR (BN + 8)   // 72 floats, 288B (16B multiple)
// 256 threads = 8 warps in 4(m) x 2(n); warp tile 32x32

// ---------------- kernel 3: fused GEMM1 + SiLU, cp.async double-buffered ----------------
// dyn smem layout: As[2][BM][36] | Bs1[2][BK][72] | Bs2[2][BK][72]
#define G1_SMEM ((2*BM*AS_STR + 4*BK*BS_STR) * 4)
__global__ __launch_bounds__(256, 2) void gemm_h_fused_kernel() {
    const int e  = blockIdx.z;
    const int M  = g_rowcnt[e];
    const int m0 = blockIdx.y * BM;
    if (m0 >= M) return;
    const int n0 = blockIdx.x * BN;

    extern __shared__ float sm[];
    float* Asm = sm;                              // 2*BM*AS_STR
    float* Bs1 = sm + 2 * BM * AS_STR;            // 2*BK*BS_STR
    float* Bs2 = Bs1 + 2 * BK * BS_STR;           // 2*BK*BS_STR
    __shared__ int stok[BM];

    const int t = threadIdx.x;
    if (t < BM) {
        int r = m0 + t;
        stok[t] = (r < M) ? g_rowtok[e][r] : -1;
    }
    __syncthreads();

    const float* Bg = g_w1r + (size_t)e * DDIM * (2 * HDIM);

    const int la_row = t >> 3;          // 0..31
    const int la_k   = (t & 7) << 2;    // 0,4,...,28
    const int lb_k   = t >> 3;          // 0..31
    const int lb_n   = (t & 7) << 3;    // 0,8,...,56

    int tokp[4];
#pragma unroll
    for (int p = 0; p < 4; p++) tokp[p] = stok[p * 32 + la_row];

    auto load_tile = [&](int s, int k0) {
#pragma unroll
        for (int p = 0; p < 4; p++) {
            int row = p * 32 + la_row;
            int tok = tokp[p];
            uint32_t dst = sptr(&Asm[s * BM * AS_STR + row * AS_STR + la_k]);
            const float* src = (tok >= 0) ? (g_xr + (size_t)tok * DDIM + k0 + la_k) : g_xr;
            cp_async16(dst, src, tok >= 0 ? 16 : 0);
        }
        const float* brow = Bg + (size_t)(k0 + lb_k) * (2 * HDIM) + n0 + lb_n;
        uint32_t d1 = sptr(&Bs1[s * BK * BS_STR + lb_k * BS_STR + lb_n]);
        uint32_t d2 = sptr(&Bs2[s * BK * BS_STR + lb_k * BS_STR + lb_n]);
        cp_async16(d1,      brow,            16);
        cp_async16(d1 + 16, brow + 4,        16);
        cp_async16(d2,      brow + HDIM,     16);
        cp_async16(d2 + 16, brow + HDIM + 4, 16);
    };

    float accU[8][4], accG[8][4];
#pragma unroll
    for (int i = 0; i < 8; i++)
#pragma unroll
        for (int j = 0; j < 4; j++) { accU[i][j] = 0.f; accG[i][j] = 0.f; }

    const int warp = t >> 5, lane = t & 31;
    const int wm = warp & 3, wn = warp >> 2;
    const int gid = lane >> 2, tg = lane & 3;

    const int NT = DDIM / BK;   // 24
    load_tile(0, 0);
    cp_commit();

    for (int kt = 0; kt < NT; kt++) {
        const int cur = kt & 1;
        if (kt + 1 < NT) { load_tile((kt + 1) & 1, (kt + 1) * BK); cp_commit(); cp_wait1(); }
        else             { cp_wait0(); }
        __syncthreads();

        const float* A  = &Asm[cur * BM * AS_STR];
        const float* B1 = &Bs1[cur * BK * BS_STR];
        const float* B2 = &Bs2[cur * BK * BS_STR];
#pragma unroll
        for (int ks = 0; ks < 4; ks++) {
            const int kk = ks * 8;
            unsigned a[2][4], b1[4][2], b2[4][2];
#pragma unroll
            for (int mt = 0; mt < 2; mt++) {
                int rm = wm * 32 + mt * 16;
                a[mt][0] = fau(A[(rm + gid) * AS_STR + kk + tg]);
                a[mt][1] = fau(A[(rm + 8 + gid) * AS_STR + kk + tg]);
                a[mt][2] = fau(A[(rm + gid) * AS_STR + kk + tg + 4]);
                a[mt][3] = fau(A[(rm + 8 + gid) * AS_STR + kk + tg + 4]);
            }
#pragma unroll
            for (int nt = 0; nt < 4; nt++) {
                int nn = wn * 32 + nt * 8;
                b1[nt][0] = fau(B1[(kk + tg) * BS_STR + nn + gid]);
                b1[nt][1] = fau(B1[(kk + tg + 4) * BS_STR + nn + gid]);
                b2[nt][0] = fau(B2[(kk + tg) * BS_STR + nn + gid]);
                b2[nt][1] = fau(B2[(kk + tg + 4) * BS_STR + nn + gid]);
            }
#pragma unroll
            for (int mt = 0; mt < 2; mt++)
#pragma unroll
                for (int nt = 0; nt < 4; nt++) {
                    mma_tf32(accU[mt * 4 + nt], a[mt], b1[nt]);
                    mma_tf32(accG[mt * 4 + nt], a[mt], b2[nt]);
                }
        }
        __syncthreads();
    }

    // epilogue: act = U * silu(G), tf32-rounded -> g_act
#pragma unroll
    for (int mt = 0; mt < 2; mt++) {
        int r0 = m0 + wm * 32 + mt * 16 + gid;
#pragma unroll
        for (int nt = 0; nt < 4; nt++) {
            int col = n0 + wn * 32 + nt * 8 + 2 * tg;
            float* u = accU[mt * 4 + nt];
            float* g = accG[mt * 4 + nt];
            if (r0 < M) {
                float2 v;
                v.x = tf32r(u[0] * (g[0] / (1.f + expf(-g[0]))));
                v.y = tf32r(u[1] * (g[1] / (1.f + expf(-g[1]))));
                *(float2*)&g_act[e][r0][col] = v;
            }
            if (r0 + 8 < M) {
                float2 v;
                v.x = tf32r(u[2] * (g[2] / (1.f + expf(-g[2]))));
                v.y = tf32r(u[3] * (g[3] / (1.f + expf(-g[3]))));
                *(float2*)&g_act[e][r0 + 8][col] = v;
            }
        }
    }
}

// ---------------- kernel 4: y = act @ W2[e], weighted atomic scatter to out ----------------
// dyn smem layout: As[2][BM][36] | Bs[2][BK][72]
#define G2_SMEM ((2*BM*AS_STR + 2*BK*BS_STR) * 4)
__global__ __launch_bounds__(256, 2) void gemm_o_kernel(float* __restrict__ out) {
    const int e  = blockIdx.z;
    const int M  = g_rowcnt[e];
    const int m0 = blockIdx.y * BM;
    if (m0 >= M) return;
    const int n0 = blockIdx.x * BN;

    extern __shared__ float sm[];
    float* Asm = sm;
    float* Bs  = sm + 2 * BM * AS_STR;

    const int t = threadIdx.x;
    const float* Bg = g_w2r + (size_t)e * HDIM * DDIM;

    const int la_row = t >> 3;
    const int la_k   = (t & 7) << 2;
    const int lb_k   = t >> 3;
    const int lb_n   = (t & 7) << 3;

    auto load_tile = [&](int s, int k0) {
#pragma unroll
        for (int p = 0; p < 4; p++) {
            int row = p * 32 + la_row;
            bool ok = (m0 + row) < M;
            uint32_t dst = sptr(&Asm[s * BM * AS_STR + row * AS_STR + la_k]);
            const float* src = ok ? &g_act[e][m0 + row][k0 + la_k] : &g_act[0][0][0];
            cp_async16(dst, src, ok ? 16 : 0);
        }
        const float* brow = Bg + (size_t)(k0 + lb_k) * DDIM + n0 + lb_n;
        uint32_t d1 = sptr(&Bs[s * BK * BS_STR + lb_k * BS_STR + lb_n]);
        cp_async16(d1,      brow,     16);
        cp_async16(d1 + 16, brow + 4, 16);
    };

    float acc[8][4];
#pragma unroll
    for (int i = 0; i < 8; i++)
#pragma unroll
        for (int j = 0; j < 4; j++) acc[i][j] = 0.f;

    const int warp = t >> 5, lane = t & 31;
    const int wm = warp & 3, wn = warp >> 2;
    const int gid = lane >> 2, tg = lane & 3;

    const int NT = HDIM / BK;   // 64
    load_tile(0, 0);
    cp_commit();

    for (int kt = 0; kt < NT; kt++) {
        const int cur = kt & 1;
        if (kt + 1 < NT) { load_tile((kt + 1) & 1, (kt + 1) * BK); cp_commit(); cp_wait1(); }
        else             { cp_wait0(); }
        __syncthreads();

        const float* A = &Asm[cur * BM * AS_STR];
        const float* B = &Bs[cur * BK * BS_STR];
#pragma unroll
        for (int ks = 0; ks < 4; ks++) {
            const int kk = ks * 8;
            unsigned a[2][4], b[4][2];
#pragma unroll
            for (int mt = 0; mt < 2; mt++) {
                int rm = wm * 32 + mt * 16;
                a[mt][0] = fau(A[(rm + gid) * AS_STR + kk + tg]);
                a[mt][1] = fau(A[(rm + 8 + gid) * AS_STR + kk + tg]);
                a[mt][2] = fau(A[(rm + gid) * AS_STR + kk + tg + 4]);
                a[mt][3] = fau(A[(rm + 8 + gid) * AS_STR + kk + tg + 4]);
            }
#pragma unroll
            for (int nt = 0; nt < 4; nt++) {
                int nn = wn * 32 + nt * 8;
                b[nt][0] = fau(B[(kk + tg) * BS_STR + nn + gid]);
                b[nt][1] = fau(B[(kk + tg + 4) * BS_STR + nn + gid]);
            }
#pragma unroll
            for (int mt = 0; mt < 2; mt++)
#pragma unroll
                for (int nt = 0; nt < 4; nt++)
                    mma_tf32(acc[mt * 4 + nt], a[mt], b[nt]);
        }
        __syncthreads();
    }

    // epilogue: weighted atomic scatter into out.
    // Each (token, col) receives at most 2 contributions (k=0, k=1); fp add is
    // commutative, so the result is bitwise deterministic regardless of order.
#pragma unroll
    for (int mt = 0; mt < 2; mt++) {
        int rA = m0 + wm * 32 + mt * 16 + gid;
        int rB = rA + 8;
        float wA = 0.f, wB = 0.f;
        int tokA = 0, tokB = 0;
        if (rA < M) { wA = g_roww[e][rA]; tokA = g_rowtok[e][rA]; }
        if (rB < M) { wB = g_roww[e][rB]; tokB = g_rowtok[e][rB]; }
#pragma unroll
        for (int nt = 0; nt < 4; nt++) {
            int col = n0 + wn * 32 + nt * 8 + 2 * tg;
            float* c = acc[mt * 4 + nt];
            if (rA < M) {
                atomicAdd(&out[(size_t)tokA * DDIM + col],     wA * c[0]);
                atomicAdd(&out[(size_t)tokA * DDIM + col + 1], wA * c[1]);
            }
            if (rB < M) {
                atomicAdd(&out[(size_t)tokB * DDIM + col],     wB * c[2]);
                atomicAdd(&out[(size_t)tokB * DDIM + col + 1], wB * c[3]);
            }
        }
    }
}

// ---------------- launch ----------------
extern "C" void kernel_launch(void* const* d_in, const int* in_sizes, int n_in,
                              void* d_out, int out_size) {
    const float* x  = (const float*)d_in[0];   // (2,2048,768) f32
    const float* Wg = (const float*)d_in[1];   // (768,8)      f32
    const float* W1 = (const float*)d_in[2];   // (8,768,4096) f32
    const float* W2 = (const float*)d_in[3];   // (8,2048,768) f32
    float* out = (float*)d_out;                // (2,2048,768) f32

    cudaFuncSetAttribute(gemm_h_fused_kernel,
                         cudaFuncAttributeMaxDynamicSharedMemorySize, G1_SMEM);
    cudaFuncSetAttribute(gemm_o_kernel,
                         cudaFuncAttributeMaxDynamicSharedMemorySize, G2_SMEM);

    preround_kernel<<<4096, 256>>>(x, W1, W2, out);
    router_kernel<<<(NTOK * 32) / 256, 256>>>(x, Wg);
    count_kernel<<<32, 256>>>();
    fill_kernel<<<16, 256>>>();
    gemm_h_fused_kernel<<<dim3(HDIM / BN, (MAXROWS + BM - 1) / BM, NEXP), 256, G1_SMEM>>>();
    gemm_o_kernel<<<dim3(DDIM / BN, (MAXROWS + BM - 1) / BM, NEXP), 256, G2_SMEM>>>(out);
}

// round 9
// speedup vs baseline: 1.0666x; 1.0013x over previous
#include <cuda_runtime.h>
#include <cuda_bf16.h>
#include <math.h>
#include <stdint.h>

// ---------------- problem constants ----------------
#define NTOK 4096          // B*L
#define DDIM 768           // D
#define NEXP 8             // E
#define HDIM 2048          // H
#define CAP  614           // int(1.2*4096/8)
#define MAXROWS (2*CAP)    // 1228 rows per expert max (k=0 and k=1 slots)

#define NX  (NTOK*DDIM)            // 3,145,728
#define NW1 (NEXP*DDIM*2*HDIM)     // 25,165,824
#define NW2 (NEXP*HDIM*DDIM)       // 12,582,912

// ---------------- device scratch (static, no allocs) ----------------
__device__ int   g_ridx[NTOK][2];
__device__ float g_rw[NTOK][2];
__device__ int   g_rowtok[NEXP][MAXROWS];
__device__ float g_roww[NEXP][MAXROWS];
__device__ int   g_rowcnt[NEXP];
__device__ float g_act[NEXP][MAXROWS][HDIM];   // ~80 MB (tf32-rounded)
__device__ float g_xr[NX];                     // tf32-rounded x   (~12.6 MB)
__device__ float g_w1r[NW1];                   // tf32-rounded W1  (~100 MB)
__device__ float g_w2r[NW2];                   // tf32-rounded W2  (~50 MB)

// ---------------- helpers ----------------
__device__ __forceinline__ float tf32r(float x) {
    unsigned r;
    asm("cvt.rna.tf32.f32 %0, %1;" : "=r"(r) : "f"(x));
    return __uint_as_float(r);
}
__device__ __forceinline__ unsigned fau(float x) { return __float_as_uint(x); }

__device__ __forceinline__ void mma_tf32(float c[4], const unsigned a[4], const unsigned b[2]) {
    asm volatile(
        "mma.sync.aligned.m16n8k8.row.col.f32.tf32.tf32.f32 "
        "{%0,%1,%2,%3}, {%4,%5,%6,%7}, {%8,%9}, {%0,%1,%2,%3};"
        : "+f"(c[0]), "+f"(c[1]), "+f"(c[2]), "+f"(c[3])
        : "r"(a[0]), "r"(a[1]), "r"(a[2]), "r"(a[3]), "r"(b[0]), "r"(b[1]));
}

__device__ __forceinline__ uint32_t sptr(const void* p) {
    return (uint32_t)__cvta_generic_to_shared(p);
}
// 16-byte async copy; sz=0 -> zero-fill destination
__device__ __forceinline__ void cp_async16(uint32_t dst, const void* src, int sz) {
    asm volatile("cp.async.cg.shared.global [%0], [%1], 16, %2;"
                 :: "r"(dst), "l"(src), "r"(sz));
}
__device__ __forceinline__ void cp_commit() { asm volatile("cp.async.commit_group;"); }
__device__ __forceinline__ void cp_wait1()  { asm volatile("cp.async.wait_group 1;"); }
__device__ __forceinline__ void cp_wait0()  { asm volatile("cp.async.wait_group 0;"); }

// vectorized no-return atomic add of 2 adjacent floats (8B-aligned)
__device__ __forceinline__ void red_add_v2(float* addr, float a, float b) {
    asm volatile("red.global.add.v2.f32 [%0], {%1, %2};"
                 :: "l"(addr), "f"(a), "f"(b) : "memory");
}

// ---------------- kernel 0: pre-round x/W1/W2 to tf32, zero out ----------------
__global__ void preround_kernel(const float* __restrict__ x,
                                const float* __restrict__ W1,
                                const float* __restrict__ W2,
                                float* __restrict__ out) {
    const int gtid = blockIdx.x * blockDim.x + threadIdx.x;
    const int n4x = NX / 4, n4w1 = NW1 / 4, n4w2 = NW2 / 4, n4o = NTOK * DDIM / 4;
    const int total = n4x + n4w1 + n4w2 + n4o;
    for (int i = gtid; i < total; i += gridDim.x * blockDim.x) {
        if (i < n4x + n4w1 + n4w2) {
            const float4* src; float4* dst; int j;
            if (i < n4x)              { src = (const float4*)x;  dst = (float4*)g_xr;  j = i; }
            else if (i < n4x + n4w1)  { src = (const float4*)W1; dst = (float4*)g_w1r; j = i - n4x; }
            else                      { src = (const float4*)W2; dst = (float4*)g_w2r; j = i - n4x - n4w1; }
            float4 v = src[j];
            dst[j] = make_float4(tf32r(v.x), tf32r(v.y), tf32r(v.z), tf32r(v.w));
        } else {
            ((float4*)out)[i - (n4x + n4w1 + n4w2)] = make_float4(0.f, 0.f, 0.f, 0.f);
        }
    }
}

// ---------------- kernel 1: router (one warp per token) ----------------
__global__ __launch_bounds__(256) void router_kernel(const float* __restrict__ x,
                                                     const float* __restrict__ Wg) {
    int warp = (blockIdx.x * blockDim.x + threadIdx.x) >> 5;
    int lane = threadIdx.x & 31;
    if (warp >= NTOK) return;
    const float* xr = x + (size_t)warp * DDIM;
    float acc[NEXP];
#pragma unroll
    for (int e = 0; e < NEXP; e++) acc[e] = 0.f;
    for (int d = lane; d < DDIM; d += 32) {
        float xv = xr[d];
        const float* wr = Wg + d * NEXP;
#pragma unroll
        for (int e = 0; e < NEXP; e++) acc[e] += xv * wr[e];
    }
#pragma unroll
    for (int off = 16; off; off >>= 1) {
#pragma unroll
        for (int e = 0; e < NEXP; e++)
            acc[e] += __shfl_xor_sync(0xffffffffu, acc[e], off);
    }
    if (lane == 0) {
        int e0 = 0; float s0 = acc[0];
#pragma unroll
        for (int e = 1; e < NEXP; e++) if (acc[e] > s0) { s0 = acc[e]; e0 = e; }
        int e1 = -1; float s1 = -INFINITY;
#pragma unroll
        for (int e = 0; e < NEXP; e++) {
            if (e == e0) continue;
            if (acc[e] > s1) { s1 = acc[e]; e1 = e; }
        }
        float x1 = expf(s1 - s0);
        float inv = 1.f / (1.f + x1);
        g_ridx[warp][0] = e0; g_ridx[warp][1] = e1;
        g_rw[warp][0] = inv;  g_rw[warp][1] = x1 * inv;
    }
}

// ---------------- kernel 2: fill rows (one block per (k,e) channel, self-contained) ----
// Each block scans BOTH router columns (int2): a stable prefix over its own channel
// membership (identical to the reference cumsum ordering) and a plain total over the
// other channel (needed for the k=1 base offset / rowcnt). No cross-kernel deps.
__global__ __launch_bounds__(256) void fill_kernel() {
    const int c = blockIdx.x;          // 0..15
    const int k = c >> 3, e = c & 7;
    const int t = threadIdx.x;
    const int lane = t & 31, wid = t >> 5;

    __shared__ int wsum[8];
    __shared__ int osum;   // other-channel total for this expert
    __shared__ int tot;    // own-channel total
    if (t == 0) osum = 0;
    __syncthreads();

    // per-thread membership over its 16 consecutive tokens
    const int tok0 = t * 16;
    int flags = 0, cnt = 0, oth = 0;
#pragma unroll
    for (int i = 0; i < 16; i++) {
        int2 r = *(const int2*)&g_ridx[tok0 + i][0];
        int own = ((k == 0 ? r.x : r.y) == e);
        int o   = ((k == 0 ? r.y : r.x) == e);
        flags |= own << i;
        cnt += own;
        oth += o;
    }
    // other-channel total: warp reduce + shared accumulate
    int or_ = oth;
#pragma unroll
    for (int off = 16; off; off >>= 1) or_ += __shfl_xor_sync(0xffffffffu, or_, off);
    if (lane == 0) atomicAdd(&osum, or_);

    // own-channel inclusive warp scan
    int v = cnt;
#pragma unroll
    for (int off = 1; off < 32; off <<= 1) {
        int n = __shfl_up_sync(0xffffffffu, v, off);
        if (lane >= off) v += n;
    }
    if (lane == 31) wsum[wid] = v;
    __syncthreads();
    if (t == 0) {
        int s = 0;
#pragma unroll
        for (int i = 0; i < 8; i++) { int x = wsum[i]; wsum[i] = s; s += x; }
        tot = s;
    }
    __syncthreads();
    int pos = wsum[wid] + v - cnt;     // channel-relative exclusive prefix (token-order stable)

    const int base = (k == 1) ? min(osum, CAP) : 0;   // k=1 rows follow kept k=0 rows
#pragma unroll
    for (int i = 0; i < 16; i++) {
        if ((flags >> i) & 1) {
            if (pos < CAP) {
                int r = base + pos;
                g_rowtok[e][r] = tok0 + i;
                g_roww[e][r] = g_rw[tok0 + i][k];
            }
            pos++;
        }
    }
    if (t == 0 && k == 0)
        g_rowcnt[e] = min(tot, CAP) + min(osum, CAP);
}

// ---------------- GEMM tile config ----------------
#define BM 128
#define BN 64
#define BK 32
#define AS_STR (BK + 4)   // 36 floats, 144B (16B multiple)
#define BS_STR (BN + 8)   // 72 floats, 288B (16B multiple)
// 256 threads = 8 warps in 4(m) x 2(n); warp tile 32x32

// ---------------- kernel 3: fused GEMM1 + SiLU, cp.async double-buffered ----------------
// dyn smem layout: As[2][BM][36] | Bs1[2][BK][72] | Bs2[2][BK][72]
#define G1_SMEM ((2*BM*AS_STR + 4*BK*BS_STR) * 4)
__global__ __launch_bounds__(256, 2) void gemm_h_fused_kernel() {
    const int e  = blockIdx.z;
    const int M  = g_rowcnt[e];
    const int m0 = blockIdx.y * BM;
    if (m0 >= M) return;
    const int n0 = blockIdx.x * BN;

    extern __shared__ float sm[];
    float* Asm = sm;                              // 2*BM*AS_STR
    float* Bs1 = sm + 2 * BM * AS_STR;            // 2*BK*BS_STR
    float* Bs2 = Bs1 + 2 * BK * BS_STR;           // 2*BK*BS_STR
    __shared__ int stok[BM];

    const int t = threadIdx.x;
    if (t < BM) {
        int r = m0 + t;
        stok[t] = (r < M) ? g_rowtok[e][r] : -1;
    }
    __syncthreads();

    const float* Bg = g_w1r + (size_t)e * DDIM * (2 * HDIM);

    const int la_row = t >> 3;          // 0..31
    const int la_k   = (t & 7) << 2;    // 0,4,...,28
    const int lb_k   = t >> 3;          // 0..31
    const int lb_n   = (t & 7) << 3;    // 0,8,...,56

    int tokp[4];
#pragma unroll
    for (int p = 0; p < 4; p++) tokp[p] = stok[p * 32 + la_row];

    auto load_tile = [&](int s, int k0) {
#pragma unroll
        for (int p = 0; p < 4; p++) {
            int row = p * 32 + la_row;
            int tok = tokp[p];
            uint32_t dst = sptr(&Asm[s * BM * AS_STR + row * AS_STR + la_k]);
            const float* src = (tok >= 0) ? (g_xr + (size_t)tok * DDIM + k0 + la_k) : g_xr;
            cp_async16(dst, src, tok >= 0 ? 16 : 0);
        }
        const float* brow = Bg + (size_t)(k0 + lb_k) * (2 * HDIM) + n0 + lb_n;
        uint32_t d1 = sptr(&Bs1[s * BK * BS_STR + lb_k * BS_STR + lb_n]);
        uint32_t d2 = sptr(&Bs2[s * BK * BS_STR + lb_k * BS_STR + lb_n]);
        cp_async16(d1,      brow,            16);
        cp_async16(d1 + 16, brow + 4,        16);
        cp_async16(d2,      brow + HDIM,     16);
        cp_async16(d2 + 16, brow + HDIM + 4, 16);
    };

    float accU[8][4], accG[8][4];
#pragma unroll
    for (int i = 0; i < 8; i++)
#pragma unroll
        for (int j = 0; j < 4; j++) { accU[i][j] = 0.f; accG[i][j] = 0.f; }

    const int warp = t >> 5, lane = t & 31;
    const int wm = warp & 3, wn = warp >> 2;
    const int gid = lane >> 2, tg = lane & 3;

    const int NT = DDIM / BK;   // 24
    load_tile(0, 0);
    cp_commit();

    for (int kt = 0; kt < NT; kt++) {
        const int cur = kt & 1;
        if (kt + 1 < NT) { load_tile((kt + 1) & 1, (kt + 1) * BK); cp_commit(); cp_wait1(); }
        else             { cp_wait0(); }
        __syncthreads();

        const float* A  = &Asm[cur * BM * AS_STR];
        const float* B1 = &Bs1[cur * BK * BS_STR];
        const float* B2 = &Bs2[cur * BK * BS_STR];
#pragma unroll
        for (int ks = 0; ks < 4; ks++) {
            const int kk = ks * 8;
            unsigned a[2][4], b1[4][2], b2[4][2];
#pragma unroll
            for (int mt = 0; mt < 2; mt++) {
                int rm = wm * 32 + mt * 16;
                a[mt][0] = fau(A[(rm + gid) * AS_STR + kk + tg]);
                a[mt][1] = fau(A[(rm + 8 + gid) * AS_STR + kk + tg]);
                a[mt][2] = fau(A[(rm + gid) * AS_STR + kk + tg + 4]);
                a[mt][3] = fau(A[(rm + 8 + gid) * AS_STR + kk + tg + 4]);
            }
#pragma unroll
            for (int nt = 0; nt < 4; nt++) {
                int nn = wn * 32 + nt * 8;
                b1[nt][0] = fau(B1[(kk + tg) * BS_STR + nn + gid]);
                b1[nt][1] = fau(B1[(kk + tg + 4) * BS_STR + nn + gid]);
                b2[nt][0] = fau(B2[(kk + tg) * BS_STR + nn + gid]);
                b2[nt][1] = fau(B2[(kk + tg + 4) * BS_STR + nn + gid]);
            }
#pragma unroll
            for (int mt = 0; mt < 2; mt++)
#pragma unroll
                for (int nt = 0; nt < 4; nt++) {
                    mma_tf32(accU[mt * 4 + nt], a[mt], b1[nt]);
                    mma_tf32(accG[mt * 4 + nt], a[mt], b2[nt]);
                }
        }
        __syncthreads();
    }

    // epilogue: act = U * silu(G), tf32-rounded -> g_act
#pragma unroll
    for (int mt = 0; mt < 2; mt++) {
        int r0 = m0 + wm * 32 + mt * 16 + gid;
#pragma unroll
        for (int nt = 0; nt < 4; nt++) {
            int col = n0 + wn * 32 + nt * 8 + 2 * tg;
            float* u = accU[mt * 4 + nt];
            float* g = accG[mt * 4 + nt];
            if (r0 < M) {
                float2 v;
                v.x = tf32r(u[0] * (g[0] / (1.f + expf(-g[0]))));
                v.y = tf32r(u[1] * (g[1] / (1.f + expf(-g[1]))));
                *(float2*)&g_act[e][r0][col] = v;
            }
            if (r0 + 8 < M) {
                float2 v;
                v.x = tf32r(u[2] * (g[2] / (1.f + expf(-g[2]))));
                v.y = tf32r(u[3] * (g[3] / (1.f + expf(-g[3]))));
                *(float2*)&g_act[e][r0 + 8][col] = v;
            }
        }
    }
}

// ---------------- kernel 4: y = act @ W2[e], weighted atomic scatter to out ----------------
// dyn smem layout: As[2][BM][36] | Bs[2][BK][72]
#define G2_SMEM ((2*BM*AS_STR + 2*BK*BS_STR) * 4)
__global__ __launch_bounds__(256, 2) void gemm_o_kernel(float* __restrict__ out) {
    const int e  = blockIdx.z;
    const int M  = g_rowcnt[e];
    const int m0 = blockIdx.y * BM;
    if (m0 >= M) return;
    const int n0 = blockIdx.x * BN;

    extern __shared__ float sm[];
    float* Asm = sm;
    float* Bs  = sm + 2 * BM * AS_STR;

    const int t = threadIdx.x;
    const float* Bg = g_w2r + (size_t)e * HDIM * DDIM;

    const int la_row = t >> 3;
    const int la_k   = (t & 7) << 2;
    const int lb_k   = t >> 3;
    const int lb_n   = (t & 7) << 3;

    auto load_tile = [&](int s, int k0) {
#pragma unroll
        for (int p = 0; p < 4; p++) {
            int row = p * 32 + la_row;
            bool ok = (m0 + row) < M;
            uint32_t dst = sptr(&Asm[s * BM * AS_STR + row * AS_STR + la_k]);
            const float* src = ok ? &g_act[e][m0 + row][k0 + la_k] : &g_act[0][0][0];
            cp_async16(dst, src, ok ? 16 : 0);
        }
        const float* brow = Bg + (size_t)(k0 + lb_k) * DDIM + n0 + lb_n;
        uint32_t d1 = sptr(&Bs[s * BK * BS_STR + lb_k * BS_STR + lb_n]);
        cp_async16(d1,      brow,     16);
        cp_async16(d1 + 16, brow + 4, 16);
    };

    float acc[8][4];
#pragma unroll
    for (int i = 0; i < 8; i++)
#pragma unroll
        for (int j = 0; j < 4; j++) acc[i][j] = 0.f;

    const int warp = t >> 5, lane = t & 31;
    const int wm = warp & 3, wn = warp >> 2;
    const int gid = lane >> 2, tg = lane & 3;

    const int NT = HDIM / BK;   // 64
    load_tile(0, 0);
    cp_commit();

    for (int kt = 0; kt < NT; kt++) {
        const int cur = kt & 1;
        if (kt + 1 < NT) { load_tile((kt + 1) & 1, (kt + 1) * BK); cp_commit(); cp_wait1(); }
        else             { cp_wait0(); }
        __syncthreads();

        const float* A = &Asm[cur * BM * AS_STR];
        const float* B = &Bs[cur * BK * BS_STR];
#pragma unroll
        for (int ks = 0; ks < 4; ks++) {
            const int kk = ks * 8;
            unsigned a[2][4], b[4][2];
#pragma unroll
            for (int mt = 0; mt < 2; mt++) {
                int rm = wm * 32 + mt * 16;
                a[mt][0] = fau(A[(rm + gid) * AS_STR + kk + tg]);
                a[mt][1] = fau(A[(rm + 8 + gid) * AS_STR + kk + tg]);
                a[mt][2] = fau(A[(rm + gid) * AS_STR + kk + tg + 4]);
                a[mt][3] = fau(A[(rm + 8 + gid) * AS_STR + kk + tg + 4]);
            }
#pragma unroll
            for (int nt = 0; nt < 4; nt++) {
                int nn = wn * 32 + nt * 8;
                b[nt][0] = fau(B[(kk + tg) * BS_STR + nn + gid]);
                b[nt][1] = fau(B[(kk + tg + 4) * BS_STR + nn + gid]);
            }
#pragma unroll
            for (int mt = 0; mt < 2; mt++)
#pragma unroll
                for (int nt = 0; nt < 4; nt++)
                    mma_tf32(acc[mt * 4 + nt], a[mt], b[nt]);
        }
        __syncthreads();
    }

    // epilogue: weighted vectorized atomic scatter into out.
    // Each (token, col) receives at most 2 contributions (k=0, k=1); fp add is
    // commutative, so the result is bitwise deterministic regardless of order.
#pragma unroll
    for (int mt = 0; mt < 2; mt++) {
        int rA = m0 + wm * 32 + mt * 16 + gid;
        int rB = rA + 8;
        float wA = 0.f, wB = 0.f;
        int tokA = 0, tokB = 0;
        if (rA < M) { wA = g_roww[e][rA]; tokA = g_rowtok[e][rA]; }
        if (rB < M) { wB = g_roww[e][rB]; tokB = g_rowtok[e][rB]; }
#pragma unroll
        for (int nt = 0; nt < 4; nt++) {
            int col = n0 + wn * 32 + nt * 8 + 2 * tg;   // even -> 8B-aligned
            float* c = acc[mt * 4 + nt];
            if (rA < M) red_add_v2(&out[(size_t)tokA * DDIM + col], wA * c[0], wA * c[1]);
            if (rB < M) red_add_v2(&out[(size_t)tokB * DDIM + col], wB * c[2], wB * c[3]);
        }
    }
}

// ---------------- launch ----------------
extern "C" void kernel_launch(void* const* d_in, const int* in_sizes, int n_in,
                              void* d_out, int out_size) {
    const float* x  = (const float*)d_in[0];   // (2,2048,768) f32
    const float* Wg = (const float*)d_in[1];   // (768,8)      f32
    const float* W1 = (const float*)d_in[2];   // (8,768,4096) f32
    const float* W2 = (const float*)d_in[3];   // (8,2048,768) f32
    float* out = (float*)d_out;                // (2,2048,768) f32

    cudaFuncSetAttribute(gemm_h_fused_kernel,
                         cudaFuncAttributeMaxDynamicSharedMemorySize, G1_SMEM);
    cudaFuncSetAttribute(gemm_o_kernel,
                         cudaFuncAttributeMaxDynamicSharedMemorySize, G2_SMEM);

    preround_kernel<<<4096, 256>>>(x, W1, W2, out);
    router_kernel<<<(NTOK * 32) / 256, 256>>>(x, Wg);
    fill_kernel<<<16, 256>>>();
    gemm_h_fused_kernel<<<dim3(HDIM / BN, (MAXROWS + BM - 1) / BM, NEXP), 256, G1_SMEM>>>();
    gemm_o_kernel<<<dim3(DDIM / BN, (MAXROWS + BM - 1) / BM, NEXP), 256, G2_SMEM>>>(out);
}

// round 14
// speedup vs baseline: 1.1069x; 1.0377x over previous
#include <cuda_runtime.h>
#include <cuda_bf16.h>
#include <math.h>
#include <stdint.h>

// ---------------- problem constants ----------------
#define NTOK 4096          // B*L
#define DDIM 768           // D
#define NEXP 8             // E
#define HDIM 2048          // H
#define CAP  614           // int(1.2*4096/8)
#define MAXROWS (2*CAP)    // 1228 rows per expert max (k=0 and k=1 slots)

#define NX  (NTOK*DDIM)            // 3,145,728
#define NW1 (NEXP*DDIM*2*HDIM)     // 25,165,824
#define NW2 (NEXP*HDIM*DDIM)       // 12,582,912

// ---------------- device scratch (static, no allocs) ----------------
__device__ int   g_ridx[NTOK][2];
__device__ float g_rw[NTOK][2];
__device__ int   g_rowtok[NEXP][MAXROWS];
__device__ float g_roww[NEXP][MAXROWS];
__device__ int   g_rowcnt[NEXP];
__device__ float g_act[NEXP][MAXROWS][HDIM];   // ~80 MB (tf32-rounded)
__device__ float g_xr[NX];                     // tf32-rounded x   (~12.6 MB)
__device__ float g_w1r[NW1];                   // tf32-rounded W1  (~100 MB)
__device__ float g_w2r[NW2];                   // tf32-rounded W2  (~50 MB)

// ---------------- helpers ----------------
__device__ __forceinline__ float tf32r(float x) {
    unsigned r;
    asm("cvt.rna.tf32.f32 %0, %1;" : "=r"(r) : "f"(x));
    return __uint_as_float(r);
}
__device__ __forceinline__ unsigned fau(float x) { return __float_as_uint(x); }

__device__ __forceinline__ void mma_tf32(float c[4], const unsigned a[4], const unsigned b[2]) {
    asm volatile(
        "mma.sync.aligned.m16n8k8.row.col.f32.tf32.tf32.f32 "
        "{%0,%1,%2,%3}, {%4,%5,%6,%7}, {%8,%9}, {%0,%1,%2,%3};"
        : "+f"(c[0]), "+f"(c[1]), "+f"(c[2]), "+f"(c[3])
        : "r"(a[0]), "r"(a[1]), "r"(a[2]), "r"(a[3]), "r"(b[0]), "r"(b[1]));
}

// ldmatrix x4: four 8x8 b16 (= 8x4 tf32) matrices -> exactly the m16n8k8 tf32 A fragment
__device__ __forceinline__ void ldsm_x4(unsigned r[4], uint32_t addr) {
    asm volatile("ldmatrix.sync.aligned.m8n8.x4.shared.b16 {%0,%1,%2,%3}, [%4];"
                 : "=r"(r[0]), "=r"(r[1]), "=r"(r[2]), "=r"(r[3]) : "r"(addr));
}

__device__ __forceinline__ uint32_t sptr(const void* p) {
    return (uint32_t)__cvta_generic_to_shared(p);
}
// 16-byte async copy; sz=0 -> zero-fill destination
__device__ __forceinline__ void cp_async16(uint32_t dst, const void* src, int sz) {
    asm volatile("cp.async.cg.shared.global [%0], [%1], 16, %2;"
                 :: "r"(dst), "l"(src), "r"(sz));
}
__device__ __forceinline__ void cp_commit() { asm volatile("cp.async.commit_group;"); }
__device__ __forceinline__ void cp_wait1()  { asm volatile("cp.async.wait_group 1;"); }
__device__ __forceinline__ void cp_wait0()  { asm volatile("cp.async.wait_group 0;"); }

// vectorized no-return atomic add of 2 adjacent floats (8B-aligned)
__device__ __forceinline__ void red_add_v2(float* addr, float a, float b) {
    asm volatile("red.global.add.v2.f32 [%0], {%1, %2};"
                 :: "l"(addr), "f"(a), "f"(b) : "memory");
}

// ---------------- kernel 0: pre-round x/W1/W2 to tf32, zero out ----------------
__global__ void preround_kernel(const float* __restrict__ x,
                                const float* __restrict__ W1,
                                const float* __restrict__ W2,
                                float* __restrict__ out) {
    const int gtid = blockIdx.x * blockDim.x + threadIdx.x;
    const int n4x = NX / 4, n4w1 = NW1 / 4, n4w2 = NW2 / 4, n4o = NTOK * DDIM / 4;
    const int total = n4x + n4w1 + n4w2 + n4o;
    for (int i = gtid; i < total; i += gridDim.x * blockDim.x) {
        if (i < n4x + n4w1 + n4w2) {
            const float4* src; float4* dst; int j;
            if (i < n4x)              { src = (const float4*)x;  dst = (float4*)g_xr;  j = i; }
            else if (i < n4x + n4w1)  { src = (const float4*)W1; dst = (float4*)g_w1r; j = i - n4x; }
            else                      { src = (const float4*)W2; dst = (float4*)g_w2r; j = i - n4x - n4w1; }
            float4 v = src[j];
            dst[j] = make_float4(tf32r(v.x), tf32r(v.y), tf32r(v.z), tf32r(v.w));
        } else {
            ((float4*)out)[i - (n4x + n4w1 + n4w2)] = make_float4(0.f, 0.f, 0.f, 0.f);
        }
    }
}

// ---------------- kernel 1: router (one warp per token) ----------------
__global__ __launch_bounds__(256) void router_kernel(const float* __restrict__ x,
                                                     const float* __restrict__ Wg) {
    int warp = (blockIdx.x * blockDim.x + threadIdx.x) >> 5;
    int lane = threadIdx.x & 31;
    if (warp >= NTOK) return;
    const float* xr = x + (size_t)warp * DDIM;
    float acc[NEXP];
#pragma unroll
    for (int e = 0; e < NEXP; e++) acc[e] = 0.f;
    for (int d = lane; d < DDIM; d += 32) {
        float xv = xr[d];
        const float* wr = Wg + d * NEXP;
#pragma unroll
        for (int e = 0; e < NEXP; e++) acc[e] += xv * wr[e];
    }
#pragma unroll
    for (int off = 16; off; off >>= 1) {
#pragma unroll
        for (int e = 0; e < NEXP; e++)
            acc[e] += __shfl_xor_sync(0xffffffffu, acc[e], off);
    }
    if (lane == 0) {
        int e0 = 0; float s0 = acc[0];
#pragma unroll
        for (int e = 1; e < NEXP; e++) if (acc[e] > s0) { s0 = acc[e]; e0 = e; }
        int e1 = -1; float s1 = -INFINITY;
#pragma unroll
        for (int e = 0; e < NEXP; e++) {
            if (e == e0) continue;
            if (acc[e] > s1) { s1 = acc[e]; e1 = e; }
        }
        float x1 = expf(s1 - s0);
        float inv = 1.f / (1.f + x1);
        g_ridx[warp][0] = e0; g_ridx[warp][1] = e1;
        g_rw[warp][0] = inv;  g_rw[warp][1] = x1 * inv;
    }
}

// ---------------- kernel 2: fill rows (one block per (k,e) channel, self-contained) ----
__global__ __launch_bounds__(256) void fill_kernel() {
    const int c = blockIdx.x;          // 0..15
    const int k = c >> 3, e = c & 7;
    const int t = threadIdx.x;
    const int lane = t & 31, wid = t >> 5;

    __shared__ int wsum[8];
    __shared__ int osum;   // other-channel total for this expert
    __shared__ int tot;    // own-channel total
    if (t == 0) osum = 0;
    __syncthreads();

    const int tok0 = t * 16;
    int flags = 0, cnt = 0, oth = 0;
#pragma unroll
    for (int i = 0; i < 16; i++) {
        int2 r = *(const int2*)&g_ridx[tok0 + i][0];
        int own = ((k == 0 ? r.x : r.y) == e);
        int o   = ((k == 0 ? r.y : r.x) == e);
        flags |= own << i;
        cnt += own;
        oth += o;
    }
    int or_ = oth;
#pragma unroll
    for (int off = 16; off; off >>= 1) or_ += __shfl_xor_sync(0xffffffffu, or_, off);
    if (lane == 0) atomicAdd(&osum, or_);

    int v = cnt;
#pragma unroll
    for (int off = 1; off < 32; off <<= 1) {
        int n = __shfl_up_sync(0xffffffffu, v, off);
        if (lane >= off) v += n;
    }
    if (lane == 31) wsum[wid] = v;
    __syncthreads();
    if (t == 0) {
        int s = 0;
#pragma unroll
        for (int i = 0; i < 8; i++) { int x = wsum[i]; wsum[i] = s; s += x; }
        tot = s;
    }
    __syncthreads();
    int pos = wsum[wid] + v - cnt;     // channel-relative exclusive prefix (token-order stable)

    const int base = (k == 1) ? min(osum, CAP) : 0;
#pragma unroll
    for (int i = 0; i < 16; i++) {
        if ((flags >> i) & 1) {
            if (pos < CAP) {
                int r = base + pos;
                g_rowtok[e][r] = tok0 + i;
                g_roww[e][r] = g_rw[tok0 + i][k];
            }
            pos++;
        }
    }
    if (t == 0 && k == 0)
        g_rowcnt[e] = min(tot, CAP) + min(osum, CAP);
}

// ---------------- GEMM tile config ----------------
#define BM 128
#define BN 64
#define BK 32
#define STG 3             // pipeline stages
#define AS_STR (BK + 4)   // 36 floats, 144B row stride (16B multiple, LDSM conflict-free)
#define BS_STR (BN + 8)   // 72 floats, 288B
// 256 threads = 8 warps in 4(m) x 2(n); warp tile 32x32

// ---------------- kernel 3: fused GEMM1 + SiLU, 3-stage cp.async, 1 bar/iter ----------
// dyn smem: As[3][BM][36] | Bs1[3][BK][72] | Bs2[3][BK][72]  = 108 KB
#define G1_SMEM ((STG*BM*AS_STR + 2*STG*BK*BS_STR) * 4)
__global__ __launch_bounds__(256, 2) void gemm_h_fused_kernel() {
    const int e  = blockIdx.z;
    const int M  = g_rowcnt[e];
    const int m0 = blockIdx.y * BM;
    if (m0 >= M) return;
    const int n0 = blockIdx.x * BN;

    extern __shared__ float sm[];
    float* Asm = sm;                              // STG*BM*AS_STR
    float* Bs1 = sm + STG * BM * AS_STR;          // STG*BK*BS_STR
    float* Bs2 = Bs1 + STG * BK * BS_STR;         // STG*BK*BS_STR
    __shared__ int stok[BM];

    const int t = threadIdx.x;
    if (t < BM) {
        int r = m0 + t;
        stok[t] = (r < M) ? g_rowtok[e][r] : -1;
    }
    __syncthreads();

    const float* Bg = g_w1r + (size_t)e * DDIM * (2 * HDIM);

    const int la_row = t >> 3;          // 0..31
    const int la_k   = (t & 7) << 2;    // 0,4,...,28
    const int lb_k   = t >> 3;          // 0..31
    const int lb_n   = (t & 7) << 3;    // 0,8,...,56

    int tokp[4];
#pragma unroll
    for (int p = 0; p < 4; p++) tokp[p] = stok[p * 32 + la_row];

    auto load_tile = [&](int s, int k0) {
#pragma unroll
        for (int p = 0; p < 4; p++) {
            int row = p * 32 + la_row;
            int tok = tokp[p];
            uint32_t dst = sptr(&Asm[s * BM * AS_STR + row * AS_STR + la_k]);
            const float* src = (tok >= 0) ? (g_xr + (size_t)tok * DDIM + k0 + la_k) : g_xr;
            cp_async16(dst, src, tok >= 0 ? 16 : 0);
        }
        const float* brow = Bg + (size_t)(k0 + lb_k) * (2 * HDIM) + n0 + lb_n;
        uint32_t d1 = sptr(&Bs1[s * BK * BS_STR + lb_k * BS_STR + lb_n]);
        uint32_t d2 = sptr(&Bs2[s * BK * BS_STR + lb_k * BS_STR + lb_n]);
        cp_async16(d1,      brow,            16);
        cp_async16(d1 + 16, brow + 4,        16);
        cp_async16(d2,      brow + HDIM,     16);
        cp_async16(d2 + 16, brow + HDIM + 4, 16);
    };

    float accU[8][4], accG[8][4];
#pragma unroll
    for (int i = 0; i < 8; i++)
#pragma unroll
        for (int j = 0; j < 4; j++) { accU[i][j] = 0.f; accG[i][j] = 0.f; }

    const int warp = t >> 5, lane = t & 31;
    const int wm = warp & 3, wn = warp >> 2;
    const int gid = lane >> 2, tg = lane & 3;

    // LDSM lane address components: matrix group g2 = lane>>3
    //   row = wm*32 + mt*16 + ((g2&1)<<3) + (lane&7);  col = kk + ((g2>>1)<<2)
    const int lm_row  = wm * 32 + (((lane >> 3) & 1) << 3) + (lane & 7);
    const int lm_col4 = ((lane >> 4) << 2);
    const uint32_t asm_base = sptr(Asm);

    const int NT = DDIM / BK;   // 24
    load_tile(0, 0); cp_commit();
    load_tile(1, BK); cp_commit();

    int s_cmp = 0, s_load = 2;
    for (int kt = 0; kt < NT; kt++) {
        if (kt == NT - 1) cp_wait0(); else cp_wait1();
        __syncthreads();   // publishes tile kt; retires compute of kt-1 (WAR for s_load)
        if (kt + 2 < NT) { load_tile(s_load, (kt + 2) * BK); cp_commit(); }

        const uint32_t abase = asm_base + (uint32_t)(s_cmp * BM * AS_STR) * 4u;
        const float* B1 = &Bs1[s_cmp * BK * BS_STR];
        const float* B2 = &Bs2[s_cmp * BK * BS_STR];
#pragma unroll
        for (int ks = 0; ks < 4; ks++) {
            const int kk = ks * 8;
            unsigned a[2][4], b1[4][2], b2[4][2];
#pragma unroll
            for (int mt = 0; mt < 2; mt++) {
                uint32_t addr = abase + (uint32_t)((lm_row + mt * 16) * AS_STR + kk + lm_col4) * 4u;
                ldsm_x4(a[mt], addr);
            }
#pragma unroll
            for (int nt = 0; nt < 4; nt++) {
                int nn = wn * 32 + nt * 8;
                b1[nt][0] = fau(B1[(kk + tg) * BS_STR + nn + gid]);
                b1[nt][1] = fau(B1[(kk + tg + 4) * BS_STR + nn + gid]);
                b2[nt][0] = fau(B2[(kk + tg) * BS_STR + nn + gid]);
                b2[nt][1] = fau(B2[(kk + tg + 4) * BS_STR + nn + gid]);
            }
#pragma unroll
            for (int mt = 0; mt < 2; mt++)
#pragma unroll
                for (int nt = 0; nt < 4; nt++) {
                    mma_tf32(accU[mt * 4 + nt], a[mt], b1[nt]);
                    mma_tf32(accG[mt * 4 + nt], a[mt], b2[nt]);
                }
        }
        s_cmp  = (s_cmp == STG - 1)  ? 0 : s_cmp + 1;
        s_load = (s_load == STG - 1) ? 0 : s_load + 1;
    }

    // epilogue: act = U * silu(G), tf32-rounded -> g_act
#pragma unroll
    for (int mt = 0; mt < 2; mt++) {
        int r0 = m0 + wm * 32 + mt * 16 + gid;
#pragma unroll
        for (int nt = 0; nt < 4; nt++) {
            int col = n0 + wn * 32 + nt * 8 + 2 * tg;
            float* u = accU[mt * 4 + nt];
            float* g = accG[mt * 4 + nt];
            if (r0 < M) {
                float2 v;
                v.x = tf32r(u[0] * (g[0] / (1.f + expf(-g[0]))));
                v.y = tf32r(u[1] * (g[1] / (1.f + expf(-g[1]))));
                *(float2*)&g_act[e][r0][col] = v;
            }
            if (r0 + 8 < M) {
                float2 v;
                v.x = tf32r(u[2] * (g[2] / (1.f + expf(-g[2]))));
                v.y = tf32r(u[3] * (g[3] / (1.f + expf(-g[3]))));
                *(float2*)&g_act[e][r0 + 8][col] = v;
            }
        }
    }
}

// ---------------- kernel 4: y = act @ W2[e], 3-stage, weighted atomic scatter --------
// dyn smem: As[3][BM][36] | Bs[3][BK][72] = 81 KB
#define G2_SMEM ((STG*BM*AS_STR + STG*BK*BS_STR) * 4)
__global__ __launch_bounds__(256, 2) void gemm_o_kernel(float* __restrict__ out) {
    const int e  = blockIdx.z;
    const int M  = g_rowcnt[e];
    const int m0 = blockIdx.y * BM;
    if (m0 >= M) return;
    const int n0 = blockIdx.x * BN;

    extern __shared__ float sm[];
    float* Asm = sm;
    float* Bs  = sm + STG * BM * AS_STR;

    const int t = threadIdx.x;
    const float* Bg = g_w2r + (size_t)e * HDIM * DDIM;

    const int la_row = t >> 3;
    const int la_k   = (t & 7) << 2;
    const int lb_k   = t >> 3;
    const int lb_n   = (t & 7) << 3;

    auto load_tile = [&](int s, int k0) {
#pragma unroll
        for (int p = 0; p < 4; p++) {
            int row = p * 32 + la_row;
            bool ok = (m0 + row) < M;
            uint32_t dst = sptr(&Asm[s * BM * AS_STR + row * AS_STR + la_k]);
            const float* src = ok ? &g_act[e][m0 + row][k0 + la_k] : &g_act[0][0][0];
            cp_async16(dst, src, ok ? 16 : 0);
        }
        const float* brow = Bg + (size_t)(k0 + lb_k) * DDIM + n0 + lb_n;
        uint32_t d1 = sptr(&Bs[s * BK * BS_STR + lb_k * BS_STR + lb_n]);
        cp_async16(d1,      brow,     16);
        cp_async16(d1 + 16, brow + 4, 16);
    };

    float acc[8][4];
#pragma unroll
    for (int i = 0; i < 8; i++)
#pragma unroll
        for (int j = 0; j < 4; j++) acc[i][j] = 0.f;

    const int warp = t >> 5, lane = t & 31;
    const int wm = warp & 3, wn = warp >> 2;
    const int gid = lane >> 2, tg = lane & 3;

    const int lm_row  = wm * 32 + (((lane >> 3) & 1) << 3) + (lane & 7);
    const int lm_col4 = ((lane >> 4) << 2);
    const uint32_t asm_base = sptr(Asm);

    const int NT = HDIM / BK;   // 64
    load_tile(0, 0); cp_commit();
    load_tile(1, BK); cp_commit();

    int s_cmp = 0, s_load = 2;
    for (int kt = 0; kt < NT; kt++) {
        if (kt == NT - 1) cp_wait0(); else cp_wait1();
        __syncthreads();
        if (kt + 2 < NT) { load_tile(s_load, (kt + 2) * BK); cp_commit(); }

        const uint32_t abase = asm_base + (uint32_t)(s_cmp * BM * AS_STR) * 4u;
        const float* B = &Bs[s_cmp * BK * BS_STR];
#pragma unroll
        for (int ks = 0; ks < 4; ks++) {
            const int kk = ks * 8;
            unsigned a[2][4], b[4][2];
#pragma unroll
            for (int mt = 0; mt < 2; mt++) {
                uint32_t addr = abase + (uint32_t)((lm_row + mt * 16) * AS_STR + kk + lm_col4) * 4u;
                ldsm_x4(a[mt], addr);
            }
#pragma unroll
            for (int nt = 0; nt < 4; nt++) {
                int nn = wn * 32 + nt * 8;
                b[nt][0] = fau(B[(kk + tg) * BS_STR + nn + gid]);
                b[nt][1] = fau(B[(kk + tg + 4) * BS_STR + nn + gid]);
            }
#pragma unroll
            for (int mt = 0; mt < 2; mt++)
#pragma unroll
                for (int nt = 0; nt < 4; nt++)
                    mma_tf32(acc[mt * 4 + nt], a[mt], b[nt]);
        }
        s_cmp  = (s_cmp == STG - 1)  ? 0 : s_cmp + 1;
        s_load = (s_load == STG - 1) ? 0 : s_load + 1;
    }

    // epilogue: weighted vectorized atomic scatter into out (<=2 contributions/cell;
    // fp add commutative -> bitwise deterministic).
#pragma unroll
    for (int mt = 0; mt < 2; mt++) {
        int rA = m0 + wm * 32 + mt * 16 + gid;
        int rB = rA + 8;
        float wA = 0.f, wB = 0.f;
        int tokA = 0, tokB = 0;
        if (rA < M) { wA = g_roww[e][rA]; tokA = g_rowtok[e][rA]; }
        if (rB < M) { wB = g_roww[e][rB]; tokB = g_rowtok[e][rB]; }
#pragma unroll
        for (int nt = 0; nt < 4; nt++) {
            int col = n0 + wn * 32 + nt * 8 + 2 * tg;   // even -> 8B-aligned
            float* c = acc[mt * 4 + nt];
            if (rA < M) red_add_v2(&out[(size_t)tokA * DDIM + col], wA * c[0], wA * c[1]);
            if (rB < M) red_add_v2(&out[(size_t)tokB * DDIM + col], wB * c[2], wB * c[3]);
        }
    }
}

// ---------------- launch ----------------
extern "C" void kernel_launch(void* const* d_in, const int* in_sizes, int n_in,
                              void* d_out, int out_size) {
    const float* x  = (const float*)d_in[0];   // (2,2048,768) f32
    const float* Wg = (const float*)d_in[1];   // (768,8)      f32
    const float* W1 = (const float*)d_in[2];   // (8,768,4096) f32
    const float* W2 = (const float*)d_in[3];   // (8,2048,768) f32
    float* out = (float*)d_out;                // (2,2048,768) f32

    cudaFuncSetAttribute(gemm_h_fused_kernel,
                         cudaFuncAttributeMaxDynamicSharedMemorySize, G1_SMEM);
    cudaFuncSetAttribute(gemm_o_kernel,
                         cudaFuncAttributeMaxDynamicSharedMemorySize, G2_SMEM);

    preround_kernel<<<4096, 256>>>(x, W1, W2, out);
    router_kernel<<<(NTOK * 32) / 256, 256>>>(x, Wg);
    fill_kernel<<<16, 256>>>();
    gemm_h_fused_kernel<<<dim3(HDIM / BN, (MAXROWS + BM - 1) / BM, NEXP), 256, G1_SMEM>>>();
    gemm_o_kernel<<<dim3(DDIM / BN, (MAXROWS + BM - 1) / BM, NEXP), 256, G2_SMEM>>>(out);
}